// round 12
// baseline (speedup 1.0000x reference)
#include <cuda_runtime.h>

// Problem constants
#define KC   512          // codebook size
#define DC   16           // channels
#define SV   131072       // T*H*W = 32*64*64 (per-batch spatial)  == 1<<17
#define NPOS 262144       // B * SV
#define QOUT_ELEMS 4194304

// ---- packed f32x2 helpers (sm_100+) ----
__device__ __forceinline__ unsigned long long pk2(float lo, float hi) {
    unsigned long long r;
    asm("mov.b64 %0, {%1, %2};" : "=l"(r) : "f"(lo), "f"(hi));
    return r;
}
__device__ __forceinline__ void unpk2(unsigned long long v, float& lo, float& hi) {
    asm("mov.b64 {%0, %1}, %2;" : "=f"(lo), "=f"(hi) : "l"(v));
}
__device__ __forceinline__ void fma2(unsigned long long& d, unsigned long long a, unsigned long long b) {
    asm("fma.rn.f32x2 %0, %1, %2, %3;" : "=l"(d) : "l"(a), "l"(b), "l"(d));
}

// NEON-style 16-element sum of squares: VF=4 strided lane partials
// (mul-then-add, no fma), then pairwise horizontal (l0+l1)+(l2+l3).
__device__ __forceinline__ float sumsq16_neon(const float* v) {
    float l0 = __fmul_rn(v[0], v[0]);
    float l1 = __fmul_rn(v[1], v[1]);
    float l2 = __fmul_rn(v[2], v[2]);
    float l3 = __fmul_rn(v[3], v[3]);
    #pragma unroll
    for (int i = 1; i < 4; i++) {
        l0 = __fadd_rn(l0, __fmul_rn(v[4*i + 0], v[4*i + 0]));
        l1 = __fadd_rn(l1, __fmul_rn(v[4*i + 1], v[4*i + 1]));
        l2 = __fadd_rn(l2, __fmul_rn(v[4*i + 2], v[4*i + 2]));
        l3 = __fadd_rn(l3, __fmul_rn(v[4*i + 3], v[4*i + 3]));
    }
    return __fadd_rn(__fadd_rn(l0, l1), __fadd_rn(l2, l3));
}

__global__ void vq_init_loss(float* out) {
    if (threadIdx.x == 0) out[0] = 0.0f;
}

// 2 positions per thread; 4 codes per iteration; f32x2 lanes = even/odd K
// (halves x-register cost vs code-pair packing -> (256,3) without spill).
__global__ __launch_bounds__(256, 3)
void vq_kernel(const float* __restrict__ x, const float* __restrict__ E,
               float* __restrict__ out)
{
    __shared__ float Es[KC * DC];     // row-major codebook, 32 KB
    __shared__ float Se[KC];          // ||e_k||^2, NEON lane+tree order, 16B-aligned
    __shared__ float wsum[8];

    const int tid = threadIdx.x;

    // straight copy of E into smem (row-major), vectorized
    for (int f = tid; f < 2048; f += 256)
        reinterpret_cast<float4*>(Es)[f] = reinterpret_cast<const float4*>(E)[f];
    for (int k = tid; k < KC; k += 256) {
        float er[16];
        #pragma unroll
        for (int i = 0; i < DC; i++) er[i] = E[k * DC + i];
        Se[k] = sumsq16_neon(er);
    }

    const int n0 = blockIdx.x * 512 + tid;     // position ids: n0, n0+256
    const int b0 = n0 >> 17,         s0 = n0 & (SV - 1);
    const int b1 = (n0 + 256) >> 17, s1 = (n0 + 256) & (SV - 1);

    // xx[j] = {x[2j], x[2j+1]}  (16 regs per position, not 32)
    unsigned long long xx0[8], xx1[8];
    float Sx0, Sx1;
    {
        float xs0[16], xs1[16];
        #pragma unroll
        for (int c = 0; c < DC; c++) {
            xs0[c] = x[(((b0 << 4) + c) << 17) + s0];
            xs1[c] = x[(((b1 << 4) + c) << 17) + s1];
        }
        #pragma unroll
        for (int j = 0; j < 8; j++) {
            xx0[j] = pk2(xs0[2 * j], xs0[2 * j + 1]);
            xx1[j] = pk2(xs1[2 * j], xs1[2 * j + 1]);
        }
        // ||x||^2 in NEON lane+tree order (XLA:CPU vectorized row-reduce).
        Sx0 = sumsq16_neon(xs0);
        Sx1 = sumsq16_neon(xs1);
    }   // xs dead -> registers freed before the main loop

    float* __restrict__ qout = out + 1;
    float* __restrict__ enc  = out + 1 + QOUT_ELEMS;
    const int lane  = tid & 31;
    const int wbase = blockIdx.x * 512 + (tid & ~31);

    // ---- encodings ZERO-FILL first (R7-proven): index-independent,
    //      fire-and-forget stores drain to DRAM during the argmin compute.
    //      The later 1.0 write is issued by the SAME lane (ir mod 32) that
    //      zeroed that column -> same-thread program order. STG.32 coalesced
    //      (enc base is 4B-phase misaligned; no wider stores possible).
    #pragma unroll 1
    for (int r = 0; r < 64; r++) {
        float* row = enc + (long)(wbase + ((r & 1) << 8) + (r >> 1)) * KC;
        #pragma unroll
        for (int j = 0; j < 16; j++)
            row[j * 32 + lane] = 0.0f;
    }

    __syncthreads();   // Es/Se ready

    // Argmin over 512 codes: 4 codes x 2 positions per iteration = 8
    // independent packed chains. Accumulator lanes: lo = even-k partial,
    // hi = odd-k partial; dot = fl(lo + hi). R1/R2/R4 established that the
    // argmin flip set is invariant to dot accumulation order at this
    // perturbation scale; Sx/Se NEON structure (the decisive part, R5) and
    // dist = fl( fl(Sx + Se_k) - 2*dot_k ) with single-rounded fma(-2,dot,t)
    // are unchanged. Strict < keeps first-index ties.
    float bestd0 = 3.402823466e38f, bestd1 = 3.402823466e38f;
    int   besti0 = 0,               besti1 = 0;
    #pragma unroll 2
    for (int pp = 0; pp < 128; pp++) {
        const ulonglong2* rows = reinterpret_cast<const ulonglong2*>(Es + (pp << 6));
        // 8 accumulators: a{pos}{code}
        unsigned long long a00 = 0ULL, a01 = 0ULL, a02 = 0ULL, a03 = 0ULL;
        unsigned long long a10 = 0ULL, a11 = 0ULL, a12 = 0ULL, a13 = 0ULL;
        #pragma unroll
        for (int t = 0; t < 4; t++) {
            ulonglong2 e0 = rows[t];           // code 4pp:   k 8t..8t+3
            ulonglong2 e1 = rows[t + 4];       // code 4pp+1
            ulonglong2 e2 = rows[t + 8];       // code 4pp+2
            ulonglong2 e3 = rows[t + 12];      // code 4pp+3
            fma2(a00, xx0[2 * t], e0.x);  fma2(a00, xx0[2 * t + 1], e0.y);
            fma2(a01, xx0[2 * t], e1.x);  fma2(a01, xx0[2 * t + 1], e1.y);
            fma2(a02, xx0[2 * t], e2.x);  fma2(a02, xx0[2 * t + 1], e2.y);
            fma2(a03, xx0[2 * t], e3.x);  fma2(a03, xx0[2 * t + 1], e3.y);
            fma2(a10, xx1[2 * t], e0.x);  fma2(a10, xx1[2 * t + 1], e0.y);
            fma2(a11, xx1[2 * t], e1.x);  fma2(a11, xx1[2 * t + 1], e1.y);
            fma2(a12, xx1[2 * t], e2.x);  fma2(a12, xx1[2 * t + 1], e2.y);
            fma2(a13, xx1[2 * t], e3.x);  fma2(a13, xx1[2 * t + 1], e3.y);
        }
        const float4 se = *reinterpret_cast<const float4*>(&Se[pp << 2]);
        const int k0 = pp << 2;

        float lo, hi, d;
        // pos0, codes k0..k0+3 ascending (strict <: first-index ties)
        unpk2(a00, lo, hi);
        d = __fmaf_rn(-2.0f, __fadd_rn(lo, hi), __fadd_rn(Sx0, se.x));
        if (d < bestd0) { bestd0 = d; besti0 = k0; }
        unpk2(a01, lo, hi);
        d = __fmaf_rn(-2.0f, __fadd_rn(lo, hi), __fadd_rn(Sx0, se.y));
        if (d < bestd0) { bestd0 = d; besti0 = k0 + 1; }
        unpk2(a02, lo, hi);
        d = __fmaf_rn(-2.0f, __fadd_rn(lo, hi), __fadd_rn(Sx0, se.z));
        if (d < bestd0) { bestd0 = d; besti0 = k0 + 2; }
        unpk2(a03, lo, hi);
        d = __fmaf_rn(-2.0f, __fadd_rn(lo, hi), __fadd_rn(Sx0, se.w));
        if (d < bestd0) { bestd0 = d; besti0 = k0 + 3; }
        // pos1
        unpk2(a10, lo, hi);
        d = __fmaf_rn(-2.0f, __fadd_rn(lo, hi), __fadd_rn(Sx1, se.x));
        if (d < bestd1) { bestd1 = d; besti1 = k0; }
        unpk2(a11, lo, hi);
        d = __fmaf_rn(-2.0f, __fadd_rn(lo, hi), __fadd_rn(Sx1, se.y));
        if (d < bestd1) { bestd1 = d; besti1 = k0 + 1; }
        unpk2(a12, lo, hi);
        d = __fmaf_rn(-2.0f, __fadd_rn(lo, hi), __fadd_rn(Sx1, se.z));
        if (d < bestd1) { bestd1 = d; besti1 = k0 + 2; }
        unpk2(a13, lo, hi);
        d = __fmaf_rn(-2.0f, __fadd_rn(lo, hi), __fadd_rn(Sx1, se.w));
        if (d < bestd1) { bestd1 = d; besti1 = k0 + 3; }
    }

    // ---- encodings 1.0 writes (owning lane; zeros already issued above) ----
    #pragma unroll 1
    for (int r = 0; r < 32; r++) {
        int ir0 = __shfl_sync(0xffffffffu, besti0, r);
        int ir1 = __shfl_sync(0xffffffffu, besti1, r);
        if (lane == (ir0 & 31)) enc[(long)(wbase + r) * KC + ir0] = 1.0f;
        if (lane == (ir1 & 31)) enc[(long)(wbase + 256 + r) * KC + ir1] = 1.0f;
    }

    // ---- q_out (straight-through emulation) + loss partial ----
    float lsum = 0.0f;
    const float* __restrict__ Er0 = E + besti0 * DC;
    const float* __restrict__ Er1 = E + besti1 * DC;
    #pragma unroll
    for (int j = 0; j < 8; j++) {
        float v0a, v0b, v1a, v1b;
        unpk2(xx0[j], v0a, v0b);
        unpk2(xx1[j], v1a, v1b);
        int c = 2 * j;

        float q0 = Er0[c];
        float df0 = __fsub_rn(q0, v0a);          // fl(q - x)
        lsum = __fmaf_rn(df0, df0, lsum);
        qout[(((b0 << 4) + c) << 17) + s0] = __fadd_rn(v0a, df0);
        float q0b = Er0[c + 1];
        float df0b = __fsub_rn(q0b, v0b);
        lsum = __fmaf_rn(df0b, df0b, lsum);
        qout[(((b0 << 4) + c + 1) << 17) + s0] = __fadd_rn(v0b, df0b);

        float q1 = Er1[c];
        float df1 = __fsub_rn(q1, v1a);
        lsum = __fmaf_rn(df1, df1, lsum);
        qout[(((b1 << 4) + c) << 17) + s1] = __fadd_rn(v1a, df1);
        float q1b = Er1[c + 1];
        float df1b = __fsub_rn(q1b, v1b);
        lsum = __fmaf_rn(df1b, df1b, lsum);
        qout[(((b1 << 4) + c + 1) << 17) + s1] = __fadd_rn(v1b, df1b);
    }

    // reduce loss: warp -> block -> one atomicAdd per block
    #pragma unroll
    for (int o = 16; o > 0; o >>= 1)
        lsum += __shfl_xor_sync(0xffffffffu, lsum, o);
    if (lane == 0) wsum[tid >> 5] = lsum;
    __syncthreads();
    if (tid == 0) {
        float t = 0.0f;
        #pragma unroll
        for (int w = 0; w < 8; w++) t += wsum[w];
        // loss = q_latent + 0.25*e_latent = 1.25 * mean((q - x)^2)
        atomicAdd(out, t * (1.25f / (float)(NPOS * DC)));
    }
}

extern "C" void kernel_launch(void* const* d_in, const int* in_sizes, int n_in,
                              void* d_out, int out_size)
{
    const float* x = (const float*)d_in[0];
    const float* E = (const float*)d_in[1];
    float* out = (float*)d_out;

    vq_init_loss<<<1, 32>>>(out);
    vq_kernel<<<NPOS / 512, 256>>>(x, E, out);
}

// round 13
// speedup vs baseline: 1.1070x; 1.1070x over previous
#include <cuda_runtime.h>

// Problem constants
#define KC   512          // codebook size
#define DC   16           // channels
#define SV   131072       // T*H*W = 32*64*64 (per-batch spatial)  == 1<<17
#define NPOS 262144       // B * SV
#define QOUT_ELEMS 4194304

// ---- packed f32x2 helpers (sm_100+) ----
__device__ __forceinline__ unsigned long long pk2(float lo, float hi) {
    unsigned long long r;
    asm("mov.b64 %0, {%1, %2};" : "=l"(r) : "f"(lo), "f"(hi));
    return r;
}
__device__ __forceinline__ void unpk2(unsigned long long v, float& lo, float& hi) {
    asm("mov.b64 {%0, %1}, %2;" : "=f"(lo), "=f"(hi) : "l"(v));
}
__device__ __forceinline__ void fma2(unsigned long long& d, unsigned long long a, unsigned long long b) {
    asm("fma.rn.f32x2 %0, %1, %2, %3;" : "=l"(d) : "l"(a), "l"(b), "l"(d));
}

// NEON-style 16-element sum of squares: VF=4 strided lane partials
// (mul-then-add, no fma), then pairwise horizontal (l0+l1)+(l2+l3).
__device__ __forceinline__ float sumsq16_neon(const float* v) {
    float l0 = __fmul_rn(v[0], v[0]);
    float l1 = __fmul_rn(v[1], v[1]);
    float l2 = __fmul_rn(v[2], v[2]);
    float l3 = __fmul_rn(v[3], v[3]);
    #pragma unroll
    for (int i = 1; i < 4; i++) {
        l0 = __fadd_rn(l0, __fmul_rn(v[4*i + 0], v[4*i + 0]));
        l1 = __fadd_rn(l1, __fmul_rn(v[4*i + 1], v[4*i + 1]));
        l2 = __fadd_rn(l2, __fmul_rn(v[4*i + 2], v[4*i + 2]));
        l3 = __fadd_rn(l3, __fmul_rn(v[4*i + 3], v[4*i + 3]));
    }
    return __fadd_rn(__fadd_rn(l0, l1), __fadd_rn(l2, l3));
}

__global__ void vq_init_loss(float* out) {
    if (threadIdx.x == 0) out[0] = 0.0f;
}

// R7 structure (2 pos/thread, 4 codes/iter, code-pair packing) with ONE
// change: chunk-min argmin (FMNMX tree + single chunk-id select), index
// recovered post-loop by bit-identical recomputation.
__global__ __launch_bounds__(256, 2)
void vq_kernel(const float* __restrict__ x, const float* __restrict__ E,
               float* __restrict__ out)
{
    // Packed codebook: Epk[p*8+q] = {E[2p][2q], E[2p+1][2q], E[2p][2q+1], E[2p+1][2q+1]}
    __shared__ float4 Epk[2048];      // 32 KB
    __shared__ float  Se[KC];         // 2 KB  (||e_k||^2, NEON lane+tree order), 16B-aligned
    __shared__ float  wsum[8];

    const int tid = threadIdx.x;

    for (int f = tid; f < 2048; f += 256) {
        int p  = f >> 3, q = f & 7;
        int k0 = p << 1, i0 = q << 1;
        Epk[f] = make_float4(E[k0 * DC + i0],     E[(k0 + 1) * DC + i0],
                             E[k0 * DC + i0 + 1], E[(k0 + 1) * DC + i0 + 1]);
    }
    for (int k = tid; k < KC; k += 256) {
        float er[16];
        #pragma unroll
        for (int i = 0; i < DC; i++) er[i] = E[k * DC + i];
        Se[k] = sumsq16_neon(er);
    }

    const int n0 = blockIdx.x * 512 + tid;     // position ids: n0, n0+256
    const int b0 = n0 >> 17,         s0 = n0 & (SV - 1);
    const int b1 = (n0 + 256) >> 17, s1 = (n0 + 256) & (SV - 1);

    unsigned long long xx0[16], xx1[16];
    float Sx0, Sx1;
    {
        float xs0[16], xs1[16];
        #pragma unroll
        for (int c = 0; c < DC; c++) {
            float v0 = x[(((b0 << 4) + c) << 17) + s0];
            float v1 = x[(((b1 << 4) + c) << 17) + s1];
            xs0[c] = v0; xx0[c] = pk2(v0, v0);
            xs1[c] = v1; xx1[c] = pk2(v1, v1);
        }
        // ||x||^2 in NEON lane+tree order (XLA:CPU vectorized row-reduce).
        Sx0 = sumsq16_neon(xs0);
        Sx1 = sumsq16_neon(xs1);
    }   // xs dead here -> registers freed before the main loop

    float* __restrict__ qout = out + 1;
    float* __restrict__ enc  = out + 1 + QOUT_ELEMS;
    const int lane  = tid & 31;
    const int wbase = blockIdx.x * 512 + (tid & ~31);

    // ---- encodings ZERO-FILL first (R7-proven): index-independent,
    //      fire-and-forget stores drain to DRAM during the argmin compute.
    //      The later 1.0 write is issued by the SAME lane (ir mod 32) that
    //      zeroed that column -> same-thread program order. STG.32 coalesced
    //      (enc base is 4B-phase misaligned; no wider stores possible).
    #pragma unroll 1
    for (int r = 0; r < 64; r++) {
        float* row = enc + (long)(wbase + ((r & 1) << 8) + (r >> 1)) * KC;
        #pragma unroll
        for (int j = 0; j < 16; j++)
            row[j * 32 + lane] = 0.0f;
    }

    __syncthreads();   // Epk/Se ready

    // Argmin over 512 codes: 4 codes x 2 positions per iteration =
    // 4 independent packed-FMA chains (R7). Chunk-min: strict < on the
    // 4-code fminf keeps the FIRST pp attaining the global min; the exact
    // within-pp index is recovered after the loop by recomputing the winning
    // chunk with IDENTICAL arithmetic (deterministic equality with bestd).
    // dot per (pos,code): SINGLE sequential ascending FMA chain from 0 —
    // bit-identical to Eigen gemm k-loop accumulation (aarch64 vfmaq).
    // dist = fl( fl(Sx + Se_k) - 2*dot_k ): fma(-2,dot,t) rounds once,
    // identical to the reference's subtract (2*dot exact).
    float bestd0 = 3.402823466e38f, bestd1 = 3.402823466e38f;
    int   bpp0 = 0,                 bpp1 = 0;
    #pragma unroll 2
    for (int pp = 0; pp < 128; pp++) {
        const ulonglong2* ep = reinterpret_cast<const ulonglong2*>(Epk + (pp << 4));
        unsigned long long a0 = 0ULL, a1 = 0ULL, bb0 = 0ULL, bb1 = 0ULL;
        #pragma unroll
        for (int q = 0; q < 8; q++) {
            ulonglong2 ea = ep[q];        // pair 2pp   (codes 4pp, 4pp+1)
            ulonglong2 eb = ep[q + 8];    // pair 2pp+1 (codes 4pp+2, 4pp+3)
            fma2(a0,  xx0[2 * q],     ea.x);
            fma2(a1,  xx1[2 * q],     ea.x);
            fma2(bb0, xx0[2 * q],     eb.x);
            fma2(bb1, xx1[2 * q],     eb.x);
            fma2(a0,  xx0[2 * q + 1], ea.y);
            fma2(a1,  xx1[2 * q + 1], ea.y);
            fma2(bb0, xx0[2 * q + 1], eb.y);
            fma2(bb1, xx1[2 * q + 1], eb.y);
        }
        const float4 se = *reinterpret_cast<const float4*>(&Se[pp << 2]);

        float dlo, dhi, d0, d1, d2, d3;
        // pos0
        unpk2(a0, dlo, dhi);
        d0 = __fmaf_rn(-2.0f, dlo, __fadd_rn(Sx0, se.x));
        d1 = __fmaf_rn(-2.0f, dhi, __fadd_rn(Sx0, se.y));
        unpk2(bb0, dlo, dhi);
        d2 = __fmaf_rn(-2.0f, dlo, __fadd_rn(Sx0, se.z));
        d3 = __fmaf_rn(-2.0f, dhi, __fadd_rn(Sx0, se.w));
        float m0 = fminf(fminf(d0, d1), fminf(d2, d3));
        if (m0 < bestd0) { bestd0 = m0; bpp0 = pp; }
        // pos1
        unpk2(a1, dlo, dhi);
        d0 = __fmaf_rn(-2.0f, dlo, __fadd_rn(Sx1, se.x));
        d1 = __fmaf_rn(-2.0f, dhi, __fadd_rn(Sx1, se.y));
        unpk2(bb1, dlo, dhi);
        d2 = __fmaf_rn(-2.0f, dlo, __fadd_rn(Sx1, se.z));
        d3 = __fmaf_rn(-2.0f, dhi, __fadd_rn(Sx1, se.w));
        float m1 = fminf(fminf(d0, d1), fminf(d2, d3));
        if (m1 < bestd1) { bestd1 = m1; bpp1 = pp; }
    }

    // ---- recover exact indices: recompute winning chunk (identical ops),
    //      first code with d == bestd (ascending -> first-index ties)
    int besti0, besti1;
    {
        const ulonglong2* ep = reinterpret_cast<const ulonglong2*>(Epk + (bpp0 << 4));
        unsigned long long a = 0ULL, bq = 0ULL;
        #pragma unroll
        for (int q = 0; q < 8; q++) {
            ulonglong2 ea = ep[q], eb = ep[q + 8];
            fma2(a,  xx0[2 * q],     ea.x);
            fma2(bq, xx0[2 * q],     eb.x);
            fma2(a,  xx0[2 * q + 1], ea.y);
            fma2(bq, xx0[2 * q + 1], eb.y);
        }
        const float4 se = *reinterpret_cast<const float4*>(&Se[bpp0 << 2]);
        float dlo, dhi;
        unpk2(a, dlo, dhi);
        float e0 = __fmaf_rn(-2.0f, dlo, __fadd_rn(Sx0, se.x));
        float e1 = __fmaf_rn(-2.0f, dhi, __fadd_rn(Sx0, se.y));
        unpk2(bq, dlo, dhi);
        float e2 = __fmaf_rn(-2.0f, dlo, __fadd_rn(Sx0, se.z));
        int k0 = bpp0 << 2;
        besti0 = (e0 == bestd0) ? k0 : (e1 == bestd0) ? k0 + 1
               : (e2 == bestd0) ? k0 + 2 : k0 + 3;
    }
    {
        const ulonglong2* ep = reinterpret_cast<const ulonglong2*>(Epk + (bpp1 << 4));
        unsigned long long a = 0ULL, bq = 0ULL;
        #pragma unroll
        for (int q = 0; q < 8; q++) {
            ulonglong2 ea = ep[q], eb = ep[q + 8];
            fma2(a,  xx1[2 * q],     ea.x);
            fma2(bq, xx1[2 * q],     eb.x);
            fma2(a,  xx1[2 * q + 1], ea.y);
            fma2(bq, xx1[2 * q + 1], eb.y);
        }
        const float4 se = *reinterpret_cast<const float4*>(&Se[bpp1 << 2]);
        float dlo, dhi;
        unpk2(a, dlo, dhi);
        float e0 = __fmaf_rn(-2.0f, dlo, __fadd_rn(Sx1, se.x));
        float e1 = __fmaf_rn(-2.0f, dhi, __fadd_rn(Sx1, se.y));
        unpk2(bq, dlo, dhi);
        float e2 = __fmaf_rn(-2.0f, dlo, __fadd_rn(Sx1, se.z));
        int k0 = bpp1 << 2;
        besti1 = (e0 == bestd1) ? k0 : (e1 == bestd1) ? k0 + 1
               : (e2 == bestd1) ? k0 + 2 : k0 + 3;
    }

    // ---- encodings 1.0 writes (owning lane; zeros already issued above) ----
    #pragma unroll 1
    for (int r = 0; r < 32; r++) {
        int ir0 = __shfl_sync(0xffffffffu, besti0, r);
        int ir1 = __shfl_sync(0xffffffffu, besti1, r);
        if (lane == (ir0 & 31)) enc[(long)(wbase + r) * KC + ir0] = 1.0f;
        if (lane == (ir1 & 31)) enc[(long)(wbase + 256 + r) * KC + ir1] = 1.0f;
    }

    // ---- q_out (straight-through emulation) + loss partial ----
    float lsum = 0.0f;
    const float* __restrict__ Er0 = E + besti0 * DC;
    const float* __restrict__ Er1 = E + besti1 * DC;
    #pragma unroll
    for (int c = 0; c < DC; c++) {
        float v0, v1, dummy;
        unpk2(xx0[c], v0, dummy);
        unpk2(xx1[c], v1, dummy);
        float q0 = Er0[c];
        float df0 = __fsub_rn(q0, v0);           // fl(q - x)
        lsum = __fmaf_rn(df0, df0, lsum);
        qout[(((b0 << 4) + c) << 17) + s0] = __fadd_rn(v0, df0);

        float q1 = Er1[c];
        float df1 = __fsub_rn(q1, v1);
        lsum = __fmaf_rn(df1, df1, lsum);
        qout[(((b1 << 4) + c) << 17) + s1] = __fadd_rn(v1, df1);
    }

    // reduce loss: warp -> block -> one atomicAdd per block
    #pragma unroll
    for (int o = 16; o > 0; o >>= 1)
        lsum += __shfl_xor_sync(0xffffffffu, lsum, o);
    if (lane == 0) wsum[tid >> 5] = lsum;
    __syncthreads();
    if (tid == 0) {
        float t = 0.0f;
        #pragma unroll
        for (int w = 0; w < 8; w++) t += wsum[w];
        // loss = q_latent + 0.25*e_latent = 1.25 * mean((q - x)^2)
        atomicAdd(out, t * (1.25f / (float)(NPOS * DC)));
    }
}

extern "C" void kernel_launch(void* const* d_in, const int* in_sizes, int n_in,
                              void* d_out, int out_size)
{
    const float* x = (const float*)d_in[0];
    const float* E = (const float*)d_in[1];
    float* out = (float*)d_out;

    vq_init_loss<<<1, 32>>>(out);
    vq_kernel<<<NPOS / 512, 256>>>(x, E, out);
}

// round 15
// speedup vs baseline: 1.4146x; 1.2778x over previous
#include <cuda_runtime.h>

// Problem constants
#define KC   512          // codebook size
#define DC   16           // channels
#define SV   131072       // T*H*W = 32*64*64 (per-batch spatial)  == 1<<17
#define NPOS 262144       // B * SV
#define QOUT_ELEMS 4194304

// ---- packed f32x2 helpers (sm_100+) ----
__device__ __forceinline__ unsigned long long pk2(float lo, float hi) {
    unsigned long long r;
    asm("mov.b64 %0, {%1, %2};" : "=l"(r) : "f"(lo), "f"(hi));
    return r;
}
__device__ __forceinline__ void unpk2(unsigned long long v, float& lo, float& hi) {
    asm("mov.b64 {%0, %1}, %2;" : "=f"(lo), "=f"(hi) : "l"(v));
}
__device__ __forceinline__ void fma2(unsigned long long& d, unsigned long long a, unsigned long long b) {
    asm("fma.rn.f32x2 %0, %1, %2, %3;" : "=l"(d) : "l"(a), "l"(b), "l"(d));
}

// NEON-style 16-element sum of squares: VF=4 strided lane partials
// (mul-then-add, no fma), then pairwise horizontal (l0+l1)+(l2+l3).
__device__ __forceinline__ float sumsq16_neon(const float* v) {
    float l0 = __fmul_rn(v[0], v[0]);
    float l1 = __fmul_rn(v[1], v[1]);
    float l2 = __fmul_rn(v[2], v[2]);
    float l3 = __fmul_rn(v[3], v[3]);
    #pragma unroll
    for (int i = 1; i < 4; i++) {
        l0 = __fadd_rn(l0, __fmul_rn(v[4*i + 0], v[4*i + 0]));
        l1 = __fadd_rn(l1, __fmul_rn(v[4*i + 1], v[4*i + 1]));
        l2 = __fadd_rn(l2, __fmul_rn(v[4*i + 2], v[4*i + 2]));
        l3 = __fadd_rn(l3, __fmul_rn(v[4*i + 3], v[4*i + 3]));
    }
    return __fadd_rn(__fadd_rn(l0, l1), __fadd_rn(l2, l3));
}

__global__ void vq_init_loss(float* out) {
    if (threadIdx.x == 0) out[0] = 0.0f;
}

// R7 structure (2 pos/thread, 4 codes/iter, select argmin) with ONE change:
// the encodings zero-fill is software-pipelined INTO the argmin loop
// (8 stores per iteration) so DRAM drains concurrently with fma work
// instead of as a serial prologue burst that backpressures the LSU.
__global__ __launch_bounds__(256, 2)
void vq_kernel(const float* __restrict__ x, const float* __restrict__ E,
               float* __restrict__ out)
{
    // Packed codebook: Epk[p*8+q] = {E[2p][2q], E[2p+1][2q], E[2p][2q+1], E[2p+1][2q+1]}
    __shared__ float4 Epk[2048];      // 32 KB
    __shared__ float  Se[KC];         // 2 KB  (||e_k||^2, NEON lane+tree order), 16B-aligned
    __shared__ float  wsum[8];

    const int tid = threadIdx.x;

    for (int f = tid; f < 2048; f += 256) {
        int p  = f >> 3, q = f & 7;
        int k0 = p << 1, i0 = q << 1;
        Epk[f] = make_float4(E[k0 * DC + i0],     E[(k0 + 1) * DC + i0],
                             E[k0 * DC + i0 + 1], E[(k0 + 1) * DC + i0 + 1]);
    }
    for (int k = tid; k < KC; k += 256) {
        float er[16];
        #pragma unroll
        for (int i = 0; i < DC; i++) er[i] = E[k * DC + i];
        Se[k] = sumsq16_neon(er);
    }

    const int n0 = blockIdx.x * 512 + tid;     // position ids: n0, n0+256
    const int b0 = n0 >> 17,         s0 = n0 & (SV - 1);
    const int b1 = (n0 + 256) >> 17, s1 = (n0 + 256) & (SV - 1);

    unsigned long long xx0[16], xx1[16];
    float Sx0, Sx1;
    {
        float xs0[16], xs1[16];
        #pragma unroll
        for (int c = 0; c < DC; c++) {
            float v0 = x[(((b0 << 4) + c) << 17) + s0];
            float v1 = x[(((b1 << 4) + c) << 17) + s1];
            xs0[c] = v0; xx0[c] = pk2(v0, v0);
            xs1[c] = v1; xx1[c] = pk2(v1, v1);
        }
        // ||x||^2 in NEON lane+tree order (XLA:CPU vectorized row-reduce).
        Sx0 = sumsq16_neon(xs0);
        Sx1 = sumsq16_neon(xs1);
    }   // xs dead here -> registers freed before the main loop

    float* __restrict__ qout = out + 1;
    float* __restrict__ enc  = out + 1 + QOUT_ELEMS;
    const int lane  = tid & 31;
    const int wbase = blockIdx.x * 512 + (tid & ~31);

    __syncthreads();   // Epk/Se ready

    // Argmin over 512 codes: 4 codes x 2 positions per iteration =
    // 4 independent packed-FMA chains. Each iteration ALSO issues 8 of the
    // warp's coalesced encodings zero-stores (64 rows x 16 stores over
    // 128 iterations, half a row per iteration): fire-and-forget STG.32
    // streams to DRAM underneath the compute. The later 1.0 write to
    // row[ir] is issued by the SAME lane (ir mod 32) that zeroes that
    // column -> same-thread program order keeps it ordered after the zero.
    //
    // dot per (pos,code): SINGLE sequential ascending FMA chain from 0 —
    // bit-identical to Eigen gemm k-loop accumulation (aarch64 vfmaq).
    // dist = fl( fl(Sx + Se_k) - 2*dot_k ): fma(-2,dot,t) rounds once,
    // identical to the reference's subtract (2*dot exact).
    // Strict < keeps first-index ties.
    float bestd0 = 3.402823466e38f, bestd1 = 3.402823466e38f;
    int   besti0 = 0,               besti1 = 0;
    #pragma unroll 2
    for (int pp = 0; pp < 128; pp++) {
        // -- pipelined zero-fill slice: row (pp>>1), columns half (pp&1) --
        {
            int r  = pp >> 1;                       // 0..63
            int jb = (pp & 1) << 3;                 // 0 or 8
            float* row = enc + (long)(wbase + ((r & 1) << 8) + (r >> 1)) * KC;
            #pragma unroll
            for (int j = 0; j < 8; j++)
                row[(jb + j) * 32 + lane] = 0.0f;
        }

        const ulonglong2* ep = reinterpret_cast<const ulonglong2*>(Epk + (pp << 4));
        unsigned long long a0 = 0ULL, a1 = 0ULL, bb0 = 0ULL, bb1 = 0ULL;
        #pragma unroll
        for (int q = 0; q < 8; q++) {
            ulonglong2 ea = ep[q];        // pair 2pp   (codes 4pp, 4pp+1)
            ulonglong2 eb = ep[q + 8];    // pair 2pp+1 (codes 4pp+2, 4pp+3)
            fma2(a0,  xx0[2 * q],     ea.x);
            fma2(a1,  xx1[2 * q],     ea.x);
            fma2(bb0, xx0[2 * q],     eb.x);
            fma2(bb1, xx1[2 * q],     eb.x);
            fma2(a0,  xx0[2 * q + 1], ea.y);
            fma2(a1,  xx1[2 * q + 1], ea.y);
            fma2(bb0, xx0[2 * q + 1], eb.y);
            fma2(bb1, xx1[2 * q + 1], eb.y);
        }
        const float4 se = *reinterpret_cast<const float4*>(&Se[pp << 2]);
        const int k0 = pp << 2;

        float dlo, dhi, d;
        // pos0, codes k0..k0+3 ascending (strict <: first-index ties)
        unpk2(a0, dlo, dhi);
        d = __fmaf_rn(-2.0f, dlo, __fadd_rn(Sx0, se.x));
        if (d < bestd0) { bestd0 = d; besti0 = k0; }
        d = __fmaf_rn(-2.0f, dhi, __fadd_rn(Sx0, se.y));
        if (d < bestd0) { bestd0 = d; besti0 = k0 + 1; }
        unpk2(bb0, dlo, dhi);
        d = __fmaf_rn(-2.0f, dlo, __fadd_rn(Sx0, se.z));
        if (d < bestd0) { bestd0 = d; besti0 = k0 + 2; }
        d = __fmaf_rn(-2.0f, dhi, __fadd_rn(Sx0, se.w));
        if (d < bestd0) { bestd0 = d; besti0 = k0 + 3; }
        // pos1
        unpk2(a1, dlo, dhi);
        d = __fmaf_rn(-2.0f, dlo, __fadd_rn(Sx1, se.x));
        if (d < bestd1) { bestd1 = d; besti1 = k0; }
        d = __fmaf_rn(-2.0f, dhi, __fadd_rn(Sx1, se.y));
        if (d < bestd1) { bestd1 = d; besti1 = k0 + 1; }
        unpk2(bb1, dlo, dhi);
        d = __fmaf_rn(-2.0f, dlo, __fadd_rn(Sx1, se.z));
        if (d < bestd1) { bestd1 = d; besti1 = k0 + 2; }
        d = __fmaf_rn(-2.0f, dhi, __fadd_rn(Sx1, se.w));
        if (d < bestd1) { bestd1 = d; besti1 = k0 + 3; }
    }

    // ---- encodings 1.0 writes (owning lane; zeros issued in the loop) ----
    #pragma unroll 1
    for (int r = 0; r < 32; r++) {
        int ir0 = __shfl_sync(0xffffffffu, besti0, r);
        int ir1 = __shfl_sync(0xffffffffu, besti1, r);
        if (lane == (ir0 & 31)) enc[(long)(wbase + r) * KC + ir0] = 1.0f;
        if (lane == (ir1 & 31)) enc[(long)(wbase + 256 + r) * KC + ir1] = 1.0f;
    }

    // ---- q_out (straight-through emulation) + loss partial ----
    float lsum = 0.0f;
    const float* __restrict__ Er0 = E + besti0 * DC;
    const float* __restrict__ Er1 = E + besti1 * DC;
    #pragma unroll
    for (int c = 0; c < DC; c++) {
        float v0, v1, dummy;
        unpk2(xx0[c], v0, dummy);
        unpk2(xx1[c], v1, dummy);
        float q0 = Er0[c];
        float df0 = __fsub_rn(q0, v0);           // fl(q - x)
        lsum = __fmaf_rn(df0, df0, lsum);
        qout[(((b0 << 4) + c) << 17) + s0] = __fadd_rn(v0, df0);

        float q1 = Er1[c];
        float df1 = __fsub_rn(q1, v1);
        lsum = __fmaf_rn(df1, df1, lsum);
        qout[(((b1 << 4) + c) << 17) + s1] = __fadd_rn(v1, df1);
    }

    // reduce loss: warp -> block -> one atomicAdd per block
    #pragma unroll
    for (int o = 16; o > 0; o >>= 1)
        lsum += __shfl_xor_sync(0xffffffffu, lsum, o);
    if (lane == 0) wsum[tid >> 5] = lsum;
    __syncthreads();
    if (tid == 0) {
        float t = 0.0f;
        #pragma unroll
        for (int w = 0; w < 8; w++) t += wsum[w];
        // loss = q_latent + 0.25*e_latent = 1.25 * mean((q - x)^2)
        atomicAdd(out, t * (1.25f / (float)(NPOS * DC)));
    }
}

extern "C" void kernel_launch(void* const* d_in, const int* in_sizes, int n_in,
                              void* d_out, int out_size)
{
    const float* x = (const float*)d_in[0];
    const float* E = (const float*)d_in[1];
    float* out = (float*)d_out;

    vq_init_loss<<<1, 32>>>(out);
    vq_kernel<<<NPOS / 512, 256>>>(x, E, out);
}